// round 8
// baseline (speedup 1.0000x reference)
#include <cuda_runtime.h>
#include <cuda_bf16.h>
#include <cstdint>
#include <math.h>

#define B_   16
#define N_   4096
#define C_   1152
#define H_   16
#define HD_  72
#define KV2  144
#define NCAT 1296          // C_ + KV2
#define MTOT (B_*N_)       // 65536
#define KA2  1224          // C_ + HD_  (gemm2 A width)

// ---------------- scratch (static device globals) --------------------------
__device__ float g_q[(size_t)MTOT * C_];          // 302 MB
__device__ float g_kvlin[(size_t)MTOT * KV2];     // 37.7 MB
__device__ float g_kv[B_ * HD_ * HD_];
__device__ float g_qsum[B_ * H_ * 2];
__device__ float g_ksum[B_ * 2];
__device__ float g_scaleq[B_ * H_];
__device__ float g_scalek[B_];

__device__ __nv_bfloat16 g_Xhi[(size_t)MTOT * C_];    // 151 MB
__device__ __nv_bfloat16 g_Xlo[(size_t)MTOT * C_];
__device__ __nv_bfloat16 g_B1hi[(size_t)NCAT * C_];   // Wcat^T [n][k]
__device__ __nv_bfloat16 g_B1lo[(size_t)NCAT * C_];
__device__ __nv_bfloat16 g_A2hi[(size_t)MTOT * KA2];  // [qf | vd]
__device__ __nv_bfloat16 g_A2lo[(size_t)MTOT * KA2];
__device__ __nv_bfloat16 g_B2hi[(size_t)B_ * C_ * KA2]; // [Mt | Pt] per b
__device__ __nv_bfloat16 g_B2lo[(size_t)B_ * C_ * KA2];

// ====================== PTX helpers =========================================
__device__ __forceinline__ uint32_t smem_u32(const void* p) {
    uint32_t a;
    asm("{ .reg .u64 t; cvta.to.shared.u64 t, %1; cvt.u32.u64 %0, t; }" : "=r"(a) : "l"(p));
    return a;
}
__device__ __forceinline__ void cp16(uint32_t dst, const void* src, int sz) {
    asm volatile("cp.async.cg.shared.global [%0], [%1], 16, %2;"
                 :: "r"(dst), "l"(src), "r"(sz) : "memory");
}
__device__ __forceinline__ void cp_commit() { asm volatile("cp.async.commit_group;" ::: "memory"); }
template <int NN> __device__ __forceinline__ void cp_wait() {
    asm volatile("cp.async.wait_group %0;" :: "n"(NN) : "memory");
}
__device__ __forceinline__ uint32_t swz(uint32_t off) { return off ^ ((off >> 3) & 0x70); }

__device__ __forceinline__ void ldsm4(uint32_t* r, uint32_t addr) {
    asm volatile("ldmatrix.sync.aligned.m8n8.x4.shared.b16 {%0,%1,%2,%3}, [%4];"
        : "=r"(r[0]), "=r"(r[1]), "=r"(r[2]), "=r"(r[3]) : "r"(addr));
}
__device__ __forceinline__ void mma16816(float* c, const uint32_t* a, const uint32_t* b) {
    asm volatile("mma.sync.aligned.m16n8k16.row.col.f32.bf16.bf16.f32 "
        "{%0,%1,%2,%3}, {%4,%5,%6,%7}, {%8,%9}, {%0,%1,%2,%3};"
        : "+f"(c[0]), "+f"(c[1]), "+f"(c[2]), "+f"(c[3])
        : "r"(a[0]), "r"(a[1]), "r"(a[2]), "r"(a[3]), "r"(b[0]), "r"(b[1]));
}

#define SMEM_BYTES (1024 + 3 * 32768)

// ====================== staged tile fill (cp.async, SW128) ==================
template <int KA, int NTOT>
__device__ __forceinline__ void fill_stage(
    uint32_t sb, int s, int kt,
    const __nv_bfloat16* __restrict__ Ahi, const __nv_bfloat16* __restrict__ Alo,
    int arow0,
    const __nv_bfloat16* __restrict__ Bhi, const __nv_bfloat16* __restrict__ Blo,
    size_t boff, int n0) {
    const int K3 = 3 * KA;
    uint32_t ab = sb + 1024u + (uint32_t)s * 32768u;
    uint32_t bb = ab + 16384u;
    int tid = threadIdx.x;
#pragma unroll
    for (int i = 0; i < 4; i++) {
        int q = tid + i * 256;
        int r = q >> 3, c16 = q & 7;
        int k3 = kt * 64 + c16 * 8;
        bool kin = k3 < K3;
        int pass = kin ? (k3 / KA) : 0;
        int kloc = kin ? (k3 - pass * KA) : 0;
        uint32_t sw = swz((uint32_t)(r * 128 + c16 * 16));
        const __nv_bfloat16* asrc =
            (pass == 1 ? Alo : Ahi) + (size_t)(arow0 + r) * KA + kloc;
        cp16(ab + sw, asrc, kin ? 16 : 0);
        int n = n0 + r;
        bool bin = kin && (n < NTOT);
        const __nv_bfloat16* bsrc =
            (pass == 2 ? Blo : Bhi) + boff + (size_t)(bin ? n : 0) * KA + kloc;
        cp16(bb + sw, bsrc, bin ? 16 : 0);
    }
}

// ====================== HMMA GEMM (mma.sync, 3x-bf16 split) =================
template <int KA, int KT, int NTOT, bool IS_G1>
__global__ __launch_bounds__(256, 2) void k_hgemm(
    const __nv_bfloat16* __restrict__ Ahi, const __nv_bfloat16* __restrict__ Alo,
    const __nv_bfloat16* __restrict__ Bhi, const __nv_bfloat16* __restrict__ Blo,
    float* __restrict__ out0, float* __restrict__ out1,
    const float* __restrict__ bias0, const float* __restrict__ bias1) {
    extern __shared__ char smem[];
    uint32_t sb = smem_u32(smem);
    int tid = threadIdx.x;
    int lane = tid & 31, warp = tid >> 5;
    int wm = warp & 1, wn = warp >> 1;        // warp grid 2 x 4
    int mi = lane >> 3, r8 = lane & 7;

    int n0 = blockIdx.x * 128;
    int arow0 = IS_G1 ? (int)(blockIdx.y * 128)
                      : (int)(blockIdx.z * 4096 + blockIdx.y * 128);
    size_t boff = IS_G1 ? 0 : (size_t)blockIdx.z * NTOT * KA;

    // ldmatrix per-lane offsets
    int a_row = wm * 64 + (mi & 1) * 8 + r8;   // + mt*16
    int a_k8  = (mi >> 1) * 8;                 // + kk*16
    int b_row = wn * 32 + (mi >> 1) * 8 + r8;  // + bt*16
    int b_k8  = (mi & 1) * 8;

    float acc[16][4];
#pragma unroll
    for (int i = 0; i < 16; i++)
#pragma unroll
        for (int j = 0; j < 4; j++) acc[i][j] = 0.f;

    fill_stage<KA, NTOT>(sb, 0, 0, Ahi, Alo, arow0, Bhi, Blo, boff, n0); cp_commit();
    fill_stage<KA, NTOT>(sb, 1, 1, Ahi, Alo, arow0, Bhi, Blo, boff, n0); cp_commit();

    for (int kt = 0; kt < KT; kt++) {
        int buf = kt % 3;
        if (kt + 2 < KT) {
            fill_stage<KA, NTOT>(sb, (kt + 2) % 3, kt + 2, Ahi, Alo, arow0,
                                 Bhi, Blo, boff, n0);
            cp_commit();
            cp_wait<2>();
        } else if (kt + 1 < KT) {
            cp_wait<1>();
        } else {
            cp_wait<0>();
        }
        __syncthreads();

        uint32_t ab = sb + 1024u + (uint32_t)buf * 32768u;
        uint32_t bb = ab + 16384u;
#pragma unroll
        for (int kk = 0; kk < 4; kk++) {
            uint32_t afr[4][4], bfr[2][4];
#pragma unroll
            for (int mt = 0; mt < 4; mt++)
                ldsm4(afr[mt], ab + swz((uint32_t)((a_row + mt * 16) * 128
                                                   + (kk * 16 + a_k8) * 2)));
#pragma unroll
            for (int bt = 0; bt < 2; bt++)
                ldsm4(bfr[bt], bb + swz((uint32_t)((b_row + bt * 16) * 128
                                                   + (kk * 16 + b_k8) * 2)));
#pragma unroll
            for (int mt = 0; mt < 4; mt++)
#pragma unroll
                for (int nt = 0; nt < 4; nt++)
                    mma16816(acc[mt * 4 + nt], afr[mt], &bfr[nt >> 1][(nt & 1) * 2]);
        }
        __syncthreads();
    }

    // ---- epilogue: fragment -> global (float2 stores) + fused focused-norms
    int crow = lane >> 2, ccol = (lane & 3) * 2;
    float s2a = 0.f, s6a = 0.f, s2b = 0.f, s6b = 0.f, k2 = 0.f, k6 = 0.f;
    int basecol = n0 + wn * 32 + ccol;
    int h0 = basecol / 72;
    int h1b = (h0 + 1) * 72;
#pragma unroll
    for (int mt = 0; mt < 4; mt++) {
#pragma unroll
        for (int nt = 0; nt < 4; nt++) {
            int col = n0 + wn * 32 + nt * 8 + ccol;
            const float* cp = acc[mt * 4 + nt];
#pragma unroll
            for (int half = 0; half < 2; half++) {
                int row = arow0 + wm * 64 + mt * 16 + crow + half * 8;
                float v0 = cp[half * 2], v1 = cp[half * 2 + 1];
                if (IS_G1) {
                    if (col < C_) {
                        v0 += bias0[col]; v1 += bias0[col + 1];
                        *(float2*)&out0[(size_t)row * C_ + col] = make_float2(v0, v1);
                        float r0 = fmaxf(v0, 0.f), r1 = fmaxf(v1, 0.f);
                        float p0 = r0 * r0, p1 = r1 * r1;
                        float q0 = p0 * p0 * p0, q1 = p1 * p1 * p1;
                        if (col >= h1b) { s2b += p0; s6b += q0; }
                        else            { s2a += p0; s6a += q0; }
                        if (col + 1 >= h1b) { s2b += p1; s6b += q1; }
                        else                { s2a += p1; s6a += q1; }
                    } else if (col < NCAT) {
                        int c2 = col - C_;
                        v0 += bias1[c2]; v1 += bias1[c2 + 1];
                        *(float2*)&out1[(size_t)row * KV2 + c2] = make_float2(v0, v1);
                        if (c2 < HD_) {   // k region (pairs never straddle 72)
                            float r0 = fmaxf(v0, 0.f), r1 = fmaxf(v1, 0.f);
                            float p0 = r0 * r0, p1 = r1 * r1;
                            k2 += p0 + p1;
                            k6 += p0 * p0 * p0 + p1 * p1 * p1;
                        }
                    }
                } else {
                    float2 o = make_float2(v0 + bias0[col], v1 + bias0[col + 1]);
                    *(float2*)&out0[(size_t)row * C_ + col] = o;
                }
            }
        }
    }
    if (IS_G1) {
        int b = arow0 >> 12;
        if (s2a != 0.f && h0 < H_) {
            atomicAdd(&g_qsum[(b * H_ + h0) * 2], s2a);
            atomicAdd(&g_qsum[(b * H_ + h0) * 2 + 1], s6a);
        }
        if (s2b != 0.f && h0 + 1 < H_) {
            atomicAdd(&g_qsum[(b * H_ + h0 + 1) * 2], s2b);
            atomicAdd(&g_qsum[(b * H_ + h0 + 1) * 2 + 1], s6b);
        }
        if (k2 != 0.f) {
            atomicAdd(&g_ksum[b * 2], k2);
            atomicAdd(&g_ksum[b * 2 + 1], k6);
        }
    }
}

// ====================== split / precompute kernels ==========================
__device__ __forceinline__ void split_bf16(float v, __nv_bfloat16& hi, __nv_bfloat16& lo) {
    hi = __float2bfloat16(v);
    lo = __float2bfloat16(v - __bfloat162float(hi));
}

__global__ void k_xsplit(const float* __restrict__ x) {
    size_t i = (size_t)blockIdx.x * 256 + threadIdx.x;
    __nv_bfloat16 h, l;
    split_bf16(x[i], h, l);
    g_Xhi[i] = h; g_Xlo[i] = l;
}

__global__ void k_wsplit(const float* __restrict__ wq, const float* __restrict__ wkv) {
    int i = blockIdx.x * 256 + threadIdx.x;           // over NCAT*C_
    int n = i / C_, k = i - n * C_;
    float v = (n < C_) ? wq[(size_t)k * C_ + n] : wkv[(size_t)k * KV2 + (n - C_)];
    __nv_bfloat16 h, l;
    split_bf16(v, h, l);
    g_B1hi[i] = h; g_B1lo[i] = l;
}

// qf = scaleq * relu(q)^3 -> A2 cols [0, C_)
__global__ void k_qf() {
    size_t i = (size_t)blockIdx.x * 256 + threadIdx.x;   // over MTOT*C_
    size_t row = i / C_;
    int c = (int)(i - row * C_);
    float v = g_q[i];
    float s = g_scaleq[((int)(row >> 12)) * H_ + c / HD_];
    float r = fmaxf(v, 0.f);
    float q3 = s * r * r * r;
    __nv_bfloat16 h, l;
    split_bf16(q3, h, l);
    size_t o = row * KA2 + c;
    g_A2hi[o] = h; g_A2lo[o] = l;
}

// ---------------- init ------------------------------------------------------
__global__ void k_init() {
    int i = blockIdx.x * blockDim.x + threadIdx.x;
    if (i < B_ * HD_ * HD_) g_kv[i] = 0.f;
    if (i < B_ * H_ * 2)    g_qsum[i] = 0.f;
    if (i < B_ * 2)         g_ksum[i] = 0.f;
}

__global__ void k_scales() {
    int i = threadIdx.x;
    if (i < B_ * H_) {
        float s2 = g_qsum[i * 2], s6 = g_qsum[i * 2 + 1];
        g_scaleq[i] = (s6 > 0.f) ? sqrtf(s2 / s6) : 0.f;
    } else if (i < B_ * H_ + B_) {
        int b = i - B_ * H_;
        float s2 = g_ksum[b * 2], s6 = g_ksum[b * 2 + 1];
        g_scalek[b] = (s6 > 0.f) ? sqrtf(s2 / s6) : 0.f;
    }
}

// ---------------- kv = k_f^T @ v ---------------------------------------------
__global__ __launch_bounds__(576) void k_kvacc() {
    __shared__ float ks[16][72], vs[16][72];
    int b = blockIdx.y;
    int n0 = blockIdx.x * 512;
    int tid = threadIdx.x;
    float acc[9] = {};
    int od[9], oe[9];
#pragma unroll
    for (int j = 0; j < 9; j++) { int o = tid + j * 576; od[j] = o / 72; oe[j] = o % 72; }

    for (int nt = 0; nt < 512; nt += 16) {
        __syncthreads();
        for (int e = tid; e < 16 * 72; e += 576) {
            int r = e / 72, d = e % 72;
            const float* p = g_kvlin + (size_t)(b * N_ + n0 + nt + r) * KV2;
            float kvv = p[d];
            float rr = fmaxf(kvv, 0.f);
            ks[r][d] = rr * rr * rr;
            vs[r][d] = p[72 + d];
        }
        __syncthreads();
#pragma unroll
        for (int r = 0; r < 16; r++)
#pragma unroll
            for (int j = 0; j < 9; j++) acc[j] += ks[r][od[j]] * vs[r][oe[j]];
    }
    float s = g_scalek[b];
#pragma unroll
    for (int j = 0; j < 9; j++)
        atomicAdd(&g_kv[b * 5184 + tid + j * 576], acc[j] * s);
}

// ---------------- depthwise conv -> A2 cols [C_, KA2) -------------------------
__global__ void k_dwc(const float* __restrict__ w, const float* __restrict__ bias) {
    int idx = blockIdx.x * blockDim.x + threadIdx.x;
    int d = idx % HD_;
    int t = idx / HD_;
    int n = t % N_;
    int b = t / N_;
    int y = n >> 6, xx = n & 63;
    float acc = bias[d];
#pragma unroll
    for (int ky = 0; ky < 3; ky++) {
        int yy = y + ky - 1;
        if ((unsigned)yy < 64u) {
#pragma unroll
            for (int kx = 0; kx < 3; kx++) {
                int xc = xx + kx - 1;
                if ((unsigned)xc < 64u)
                    acc += g_kvlin[(size_t)(b * N_ + yy * 64 + xc) * KV2 + 72 + d]
                         * w[d * 9 + ky * 3 + kx];
            }
        }
    }
    __nv_bfloat16 h, l;
    split_bf16(acc, h, l);
    size_t o = (size_t)(b * N_ + n) * KA2 + C_ + d;
    g_A2hi[o] = h; g_A2lo[o] = l;
}

// ---------------- proj_sum -> B2 rows [C_, KA2) for every batch ---------------
__global__ void k_projsum(const float* __restrict__ proj) {
    int idx = blockIdx.x * blockDim.x + threadIdx.x;   // 72*1152
    if (idx >= HD_ * C_) return;
    int c = idx / HD_, d = idx % HD_;
    float s = 0.f;
#pragma unroll
    for (int h = 0; h < H_; h++) s += proj[(size_t)(h * HD_ + d) * C_ + c];
    __nv_bfloat16 hh, ll;
    split_bf16(s, hh, ll);
#pragma unroll
    for (int b = 0; b < B_; b++) {
        size_t o = ((size_t)b * C_ + c) * KA2 + C_ + d;
        g_B2hi[o] = hh; g_B2lo[o] = ll;
    }
}

// ---------------- Mt[b][c][k=h*72+d] = sum_e kv[b][d][e] * proj[h*72+e][c] ----
__global__ __launch_bounds__(256) void k_mker(const float* __restrict__ proj) {
    __shared__ float kvs[72 * 72];
    int b = blockIdx.z, h = blockIdx.y, ct = blockIdx.x;
    int tid = threadIdx.x;
    for (int e = tid; e < 5184; e += 256) kvs[e] = g_kv[b * 5184 + e];
    __syncthreads();
    int c = ct * 128 + (tid & 127);
    int dbase = (tid >> 7) * 36;
    float acc[36] = {};
#pragma unroll 8
    for (int e2 = 0; e2 < 72; e2++) {
        float p = proj[(size_t)(h * HD_ + e2) * C_ + c];
#pragma unroll
        for (int dd = 0; dd < 36; dd++)
            acc[dd] += kvs[(dbase + dd) * 72 + e2] * p;
    }
    size_t base = ((size_t)b * C_ + c) * KA2 + h * HD_ + dbase;
#pragma unroll
    for (int dd = 0; dd < 36; dd++) {
        __nv_bfloat16 hh, ll;
        split_bf16(acc[dd], hh, ll);
        g_B2hi[base + dd] = hh; g_B2lo[base + dd] = ll;
    }
}

// ---------------- launch ------------------------------------------------------
extern "C" void kernel_launch(void* const* d_in, const int* in_sizes, int n_in,
                              void* d_out, int out_size) {
    const float* x      = (const float*)d_in[0];
    const float* wq_w   = (const float*)d_in[1];
    const float* wq_b   = (const float*)d_in[2];
    const float* wkv_w  = (const float*)d_in[3];
    const float* wkv_b  = (const float*)d_in[4];
    const float* dwc_w  = (const float*)d_in[5];
    const float* dwc_b  = (const float*)d_in[6];
    const float* proj_w = (const float*)d_in[7];
    const float* proj_b = (const float*)d_in[8];
    float* out = (float*)d_out;

    cudaFuncSetAttribute(k_hgemm<C_, 54, NCAT, true>,
                         cudaFuncAttributeMaxDynamicSharedMemorySize, SMEM_BYTES);
    cudaFuncSetAttribute(k_hgemm<KA2, 58, C_, false>,
                         cudaFuncAttributeMaxDynamicSharedMemorySize, SMEM_BYTES);

    __nv_bfloat16 *xhi, *xlo, *b1hi, *b1lo, *a2hi, *a2lo, *b2hi, *b2lo;
    float *gq, *gkvlin;
    cudaGetSymbolAddress((void**)&xhi,  g_Xhi);
    cudaGetSymbolAddress((void**)&xlo,  g_Xlo);
    cudaGetSymbolAddress((void**)&b1hi, g_B1hi);
    cudaGetSymbolAddress((void**)&b1lo, g_B1lo);
    cudaGetSymbolAddress((void**)&a2hi, g_A2hi);
    cudaGetSymbolAddress((void**)&a2lo, g_A2lo);
    cudaGetSymbolAddress((void**)&b2hi, g_B2hi);
    cudaGetSymbolAddress((void**)&b2lo, g_B2lo);
    cudaGetSymbolAddress((void**)&gq,     g_q);
    cudaGetSymbolAddress((void**)&gkvlin, g_kvlin);

    k_init<<<324, 256>>>();
    k_xsplit<<<(int)((MTOT * (size_t)C_) / 256), 256>>>(x);
    k_wsplit<<<(NCAT * C_) / 256, 256>>>(wq_w, wkv_w);

    // GEMM1: [x] @ [wq|wkv] -> g_q, g_kvlin  (3x-bf16, K3=3456) + fused norms
    k_hgemm<C_, 54, NCAT, true><<<dim3(11, 512), 256, SMEM_BYTES>>>(
        xhi, xlo, b1hi, b1lo, gq, gkvlin, wq_b, wkv_b);

    k_scales<<<1, 288>>>();
    k_kvacc<<<dim3(8, 16), 576>>>();
    k_dwc<<<18432, 256>>>(dwc_w, dwc_b);
    k_qf<<<(int)((MTOT * (size_t)C_) / 256), 256>>>();
    k_projsum<<<324, 256>>>(proj_w);
    k_mker<<<dim3(9, 16, 16), 256>>>(proj_w);

    // GEMM2: [qf|vd] @ [Mt|Pt]^T + proj_b -> out   (3x-bf16, K3=3672)
    k_hgemm<KA2, 58, C_, false><<<dim3(9, 32, 16), 256, SMEM_BYTES>>>(
        a2hi, a2lo, b2hi, b2lo, out, nullptr, proj_b, nullptr);
}